// round 6
// baseline (speedup 1.0000x reference)
#include <cuda_runtime.h>
#include <cuda_bf16.h>
#include <cstdint>

// ============================================================================
// LateInteractionScorer: scores[b] = sum_q max_d ( <Q[b,q], D[b,d]> + (1-mask)*(-1e30) )
// Q: [64,32,128] f32, D: [64,4096,128] f32, mask: [64,4096] i32 -> out [64] f32
//
// tcgen05 is unavailable: the harness's nvcc emits PTX for base target sm_103,
// which rejects all family-specific (sm_103a) instructions. So we use the
// base-ISA tensor path: mma.sync.m16n8k16 bf16 (HMMA). The kernel is
// DRAM-bound (~134 MB doc vectors); HMMA math is ~8 us, so memory rules.
//
// Mapping per warp: A = 16 docs x 16 dims (row-major), B = queries (col-major,
// N=8 per mma, 4 n-chunks = 32 queries), K = 128 in 8 chunks.
// Doc fragments are loaded straight from GMEM as float2 (32B-sector aligned
// per 4-lane group -> full sector utilization), converted to bf16 in regs.
// ============================================================================

static constexpr int BATCH = 64;
static constexpr int QLEN  = 32;
static constexpr int DLEN  = 4096;
static constexpr int HD    = 128;

static constexpr int SPLITS = 4;
static constexpr int DOCS_PER_SPLIT = DLEN / SPLITS;   // 1024
static constexpr int THREADS = 256;
static constexpr int WARPS   = THREADS / 32;           // 8
static constexpr int DOCS_PER_ITER = WARPS * 16;       // 128
static constexpr int ITERS = DOCS_PER_SPLIT / DOCS_PER_ITER;  // 8

static constexpr float NEGV = -1e30f;

__device__ float g_partial[BATCH * SPLITS * QLEN];

// pack two floats -> bf16x2 (lo in low 16 bits)
__device__ __forceinline__ uint32_t packbf(float lo, float hi) {
    __nv_bfloat162 h = __floats2bfloat162_rn(lo, hi);
    return *reinterpret_cast<uint32_t*>(&h);
}

// D += A * B, m16n8k16, bf16 inputs, f32 accumulate
__device__ __forceinline__ void mma16816(float* c, const uint32_t* a, const uint32_t* b) {
    asm volatile(
        "mma.sync.aligned.m16n8k16.row.col.f32.bf16.bf16.f32 "
        "{%0,%1,%2,%3}, {%4,%5,%6,%7}, {%8,%9}, {%0,%1,%2,%3};"
        : "+f"(c[0]), "+f"(c[1]), "+f"(c[2]), "+f"(c[3])
        : "r"(a[0]), "r"(a[1]), "r"(a[2]), "r"(a[3]),
          "r"(b[0]), "r"(b[1]));
}

// ---------------------------------------------------------------------------
// Main kernel: grid (SPLITS, BATCH), 256 threads
// ---------------------------------------------------------------------------
__global__ __launch_bounds__(THREADS, 2)
void li_score_kernel(const float* __restrict__ qv,
                     const float* __restrict__ dv,
                     const int*   __restrict__ mask) {
    __shared__ float red[WARPS * QLEN];

    const int tid  = threadIdx.x;
    const int wid  = tid >> 5;
    const int lane = tid & 31;
    const int g    = lane >> 2;   // groupID (row within fragment)
    const int tig  = lane & 3;    // thread-in-group (col pair)

    const int b     = blockIdx.y;
    const int split = blockIdx.x;

    const float* Qb = qv + (size_t)b * QLEN * HD;
    const float* Ds = dv + ((size_t)b * DLEN + (size_t)split * DOCS_PER_SPLIT) * HD;
    const int*   Mb = mask + (size_t)b * DLEN + split * DOCS_PER_SPLIT;

    // ---- Preload B fragments (queries), bf16x2, kept in registers ----
    // B frag for m16n8k16 col-major: b0 = {B[tig*2][g], B[tig*2+1][g]},
    //                                b1 = {B[tig*2+8][g], B[tig*2+9][g]}
    // with B[k][n] = Q[q = n*8 + g][dim = k0 + k]
    uint32_t Bf[4][8][2];
#pragma unroll
    for (int n = 0; n < 4; n++) {
        const float* qrow = Qb + (n * 8 + g) * HD;
#pragma unroll
        for (int k = 0; k < 8; k++) {
            int k0 = k * 16 + tig * 2;
            float2 lo = *(const float2*)(qrow + k0);
            float2 hi = *(const float2*)(qrow + k0 + 8);
            Bf[n][k][0] = packbf(lo.x, lo.y);
            Bf[n][k][1] = packbf(hi.x, hi.y);
        }
    }

    float qmax[8];
#pragma unroll
    for (int i = 0; i < 8; i++) qmax[i] = -3.0e38f;

    for (int it = 0; it < ITERS; it++) {
        const int dtile = it * DOCS_PER_ITER + wid * 16;
        const int r0 = dtile + g;
        const int r1 = dtile + g + 8;
        const float adj0 = Mb[r0] ? 0.0f : NEGV;
        const float adj1 = Mb[r1] ? 0.0f : NEGV;
        const float* row0 = Ds + (size_t)r0 * HD;
        const float* row1 = Ds + (size_t)r1 * HD;

        float acc[4][4];
#pragma unroll
        for (int n = 0; n < 4; n++)
#pragma unroll
            for (int i = 0; i < 4; i++) acc[n][i] = 0.0f;

#pragma unroll
        for (int k = 0; k < 8; k++) {
            const int k0 = k * 16 + tig * 2;
            // A frag (row-major 16x16): a0={A[g][c],A[g][c+1]}, a1={A[g+8][c],..},
            //                           a2={A[g][c+8],..},      a3={A[g+8][c+8],..}
            float2 a00 = *(const float2*)(row0 + k0);
            float2 a10 = *(const float2*)(row1 + k0);
            float2 a01 = *(const float2*)(row0 + k0 + 8);
            float2 a11 = *(const float2*)(row1 + k0 + 8);
            uint32_t A[4];
            A[0] = packbf(a00.x, a00.y);
            A[1] = packbf(a10.x, a10.y);
            A[2] = packbf(a01.x, a01.y);
            A[3] = packbf(a11.x, a11.y);
#pragma unroll
            for (int n = 0; n < 4; n++) mma16816(acc[n], A, Bf[n][k]);
        }

        // D frag: c0 = D[g][tig*2], c1 = D[g][tig*2+1],
        //         c2 = D[g+8][tig*2], c3 = D[g+8][tig*2+1]
        // q column for n-chunk n: q = n*8 + tig*2 + {0,1}
#pragma unroll
        for (int n = 0; n < 4; n++) {
            qmax[n * 2 + 0] = fmaxf(qmax[n * 2 + 0],
                                    fmaxf(acc[n][0] + adj0, acc[n][2] + adj1));
            qmax[n * 2 + 1] = fmaxf(qmax[n * 2 + 1],
                                    fmaxf(acc[n][1] + adj0, acc[n][3] + adj1));
        }
    }

    // ---- Max over the 8 groupIDs (lane bits [2:5)) ----
#pragma unroll
    for (int i = 0; i < 8; i++) {
#pragma unroll
        for (int o = 4; o <= 16; o <<= 1)
            qmax[i] = fmaxf(qmax[i], __shfl_xor_sync(0xffffffffu, qmax[i], o));
    }
    if (g == 0) {  // lanes 0..3, tig = lane
#pragma unroll
        for (int n = 0; n < 4; n++) {
            red[wid * QLEN + n * 8 + tig * 2 + 0] = qmax[n * 2 + 0];
            red[wid * QLEN + n * 8 + tig * 2 + 1] = qmax[n * 2 + 1];
        }
    }
    __syncthreads();

    // ---- Max across the 8 warps, write per-(batch,split) partial ----
    if (tid < QLEN) {
        float v = red[tid];
#pragma unroll
        for (int w = 1; w < WARPS; w++) v = fmaxf(v, red[w * QLEN + tid]);
        g_partial[((size_t)b * SPLITS + split) * QLEN + tid] = v;
    }
}

// ---------------------------------------------------------------------------
// Reduce kernel: out[b] = sum_q max_s partial[b][s][q]
// ---------------------------------------------------------------------------
__global__ void li_reduce_kernel(float* __restrict__ out) {
    int b = blockIdx.x;
    int q = threadIdx.x;   // 0..31
    float v = -3.4e38f;
#pragma unroll
    for (int s = 0; s < SPLITS; s++)
        v = fmaxf(v, g_partial[((size_t)b * SPLITS + s) * QLEN + q]);
#pragma unroll
    for (int o = 16; o > 0; o >>= 1)
        v += __shfl_xor_sync(0xffffffffu, v, o);
    if (q == 0) out[b] = v;
}

// ---------------------------------------------------------------------------
extern "C" void kernel_launch(void* const* d_in, const int* in_sizes, int n_in,
                              void* d_out, int out_size) {
    const float* qv   = (const float*)d_in[0];   // [64,32,128] f32
    const float* dv   = (const float*)d_in[1];   // [64,4096,128] f32
    const int*   mask = (const int*)d_in[2];     // [64,4096] i32
    float* out = (float*)d_out;                  // [64] f32

    dim3 grid(SPLITS, BATCH);
    li_score_kernel<<<grid, THREADS>>>(qv, dv, mask);
    li_reduce_kernel<<<BATCH, 32>>>(out);
}

// round 7
// speedup vs baseline: 1.1220x; 1.1220x over previous
#include <cuda_runtime.h>
#include <cuda_bf16.h>
#include <cstdint>

// ============================================================================
// LateInteractionScorer: scores[b] = sum_q max_d ( <Q[b,q], D[b,d]> + (1-mask)*(-1e30) )
// Q: [64,32,128] f32, D: [64,4096,128] f32, mask: [64,4096] i32 -> out [64] f32
//
// Base-ISA tensor path (mma.sync.m16n8k16 bf16) since the harness emits PTX for
// target sm_103 (no tcgen05). DRAM-bound: 134 MB doc stream, floor ~17 us.
//
// This round:
//  - single fused kernel (cross-split reduce via ordered-uint atomicMax +
//    last-CTA-per-batch ticket; scratch self-resets for graph replay)
//  - one LDG.128 per lane per (row, k-chunk) using a K-slot permutation shared
//    by A and B fragments (dot over K is permutation invariant)
// ============================================================================

static constexpr int BATCH = 64;
static constexpr int QLEN  = 32;
static constexpr int DLEN  = 4096;
static constexpr int HD    = 128;

static constexpr int SPLITS = 4;
static constexpr int DOCS_PER_SPLIT = DLEN / SPLITS;   // 1024
static constexpr int THREADS = 256;
static constexpr int WARPS   = THREADS / 32;           // 8
static constexpr int DOCS_PER_ITER = WARPS * 16;       // 128
static constexpr int ITERS = DOCS_PER_SPLIT / DOCS_PER_ITER;  // 8

static constexpr float NEGV = -1e30f;

// Cross-CTA scratch. Zero-initialized at module load; the last CTA per batch
// resets it after consuming, so every graph replay sees the same initial state.
// ordenc(x) > 0 for every real float, so 0 is the identity for atomicMax.
__device__ unsigned g_qmax[BATCH * QLEN];   // ordered-uint per-q running max
__device__ int      g_count[BATCH];         // arrival ticket per batch

// order-preserving float <-> uint
__device__ __forceinline__ unsigned ordenc(float f) {
    unsigned b = __float_as_uint(f);
    return (b & 0x80000000u) ? ~b : (b | 0x80000000u);
}
__device__ __forceinline__ float orddec(unsigned o) {
    unsigned b = (o & 0x80000000u) ? (o & 0x7FFFFFFFu) : ~o;
    return __uint_as_float(b);
}

// pack two floats -> bf16x2 (lo in low 16 bits)
__device__ __forceinline__ uint32_t packbf(float lo, float hi) {
    __nv_bfloat162 h = __floats2bfloat162_rn(lo, hi);
    return *reinterpret_cast<uint32_t*>(&h);
}

// D += A * B, m16n8k16, bf16 inputs, f32 accumulate
__device__ __forceinline__ void mma16816(float* c, const uint32_t* a, const uint32_t* b) {
    asm volatile(
        "mma.sync.aligned.m16n8k16.row.col.f32.bf16.bf16.f32 "
        "{%0,%1,%2,%3}, {%4,%5,%6,%7}, {%8,%9}, {%0,%1,%2,%3};"
        : "+f"(c[0]), "+f"(c[1]), "+f"(c[2]), "+f"(c[3])
        : "r"(a[0]), "r"(a[1]), "r"(a[2]), "r"(a[3]),
          "r"(b[0]), "r"(b[1]));
}

// ---------------------------------------------------------------------------
// Fused kernel: grid (SPLITS, BATCH), 256 threads
// ---------------------------------------------------------------------------
__global__ __launch_bounds__(THREADS, 2)
void li_score_kernel(const float* __restrict__ qv,
                     const float* __restrict__ dv,
                     const int*   __restrict__ mask,
                     float*       __restrict__ out) {
    __shared__ float red[WARPS * QLEN];
    __shared__ int   s_last;

    const int tid  = threadIdx.x;
    const int wid  = tid >> 5;
    const int lane = tid & 31;
    const int g    = lane >> 2;   // groupID (row within fragment)
    const int tig  = lane & 3;    // thread-in-group

    const int b     = blockIdx.y;
    const int split = blockIdx.x;

    const float* Qb = qv + (size_t)b * QLEN * HD;
    const float* Ds = dv + ((size_t)b * DLEN + (size_t)split * DOCS_PER_SPLIT) * HD;
    const int*   Mb = mask + (size_t)b * DLEN + split * DOCS_PER_SPLIT;

    // ---- Preload B fragments (queries), bf16x2, kept in registers ----
    // K-slot permutation: lane tig supplies physical dims {tig*4 .. tig*4+3}
    // into MMA k-slots {tig*2, tig*2+1, tig*2+8, tig*2+9}. A uses the same
    // permutation, so the contraction is unchanged.
    // B[k][n] with n = q%8 -> groupID g = q%8 row owner: frag row index is g.
    uint32_t Bf[4][8][2];
#pragma unroll
    for (int n = 0; n < 4; n++) {
        const float* qrow = Qb + (n * 8 + g) * HD;
#pragma unroll
        for (int k = 0; k < 8; k++) {
            float4 f = *(const float4*)(qrow + k * 16 + tig * 4);
            Bf[n][k][0] = packbf(f.x, f.y);
            Bf[n][k][1] = packbf(f.z, f.w);
        }
    }

    float qmax[8];
#pragma unroll
    for (int i = 0; i < 8; i++) qmax[i] = -3.0e38f;

    for (int it = 0; it < ITERS; it++) {
        const int dtile = it * DOCS_PER_ITER + wid * 16;
        const int r0 = dtile + g;
        const int r1 = dtile + g + 8;
        const float adj0 = Mb[r0] ? 0.0f : NEGV;
        const float adj1 = Mb[r1] ? 0.0f : NEGV;
        const float* row0 = Ds + (size_t)r0 * HD;
        const float* row1 = Ds + (size_t)r1 * HD;

        float acc[4][4];
#pragma unroll
        for (int n = 0; n < 4; n++)
#pragma unroll
            for (int i = 0; i < 4; i++) acc[n][i] = 0.0f;

#pragma unroll
        for (int k = 0; k < 8; k++) {
            const int k0 = k * 16 + tig * 4;
            float4 fa0 = *(const float4*)(row0 + k0);   // one LDG.128 per row
            float4 fa1 = *(const float4*)(row1 + k0);
            uint32_t A[4];
            A[0] = packbf(fa0.x, fa0.y);   // slots (tig*2, tig*2+1), row g
            A[1] = packbf(fa1.x, fa1.y);   // same slots, row g+8
            A[2] = packbf(fa0.z, fa0.w);   // slots (tig*2+8, tig*2+9), row g
            A[3] = packbf(fa1.z, fa1.w);   // same slots, row g+8
#pragma unroll
            for (int n = 0; n < 4; n++) mma16816(acc[n], A, Bf[n][k]);
        }

        // D frag: c0=D[g][tig*2] c1=D[g][tig*2+1] c2=D[g+8][tig*2] c3=D[g+8][tig*2+1]
#pragma unroll
        for (int n = 0; n < 4; n++) {
            qmax[n * 2 + 0] = fmaxf(qmax[n * 2 + 0],
                                    fmaxf(acc[n][0] + adj0, acc[n][2] + adj1));
            qmax[n * 2 + 1] = fmaxf(qmax[n * 2 + 1],
                                    fmaxf(acc[n][1] + adj0, acc[n][3] + adj1));
        }
    }

    // ---- Max over the 8 groupIDs (lane bits [2:5)) ----
#pragma unroll
    for (int i = 0; i < 8; i++) {
#pragma unroll
        for (int o = 4; o <= 16; o <<= 1)
            qmax[i] = fmaxf(qmax[i], __shfl_xor_sync(0xffffffffu, qmax[i], o));
    }
    if (g == 0) {  // lanes 0..3, tig = lane
#pragma unroll
        for (int n = 0; n < 4; n++) {
            red[wid * QLEN + n * 8 + tig * 2 + 0] = qmax[n * 2 + 0];
            red[wid * QLEN + n * 8 + tig * 2 + 1] = qmax[n * 2 + 1];
        }
    }
    __syncthreads();

    // ---- Max across the 8 warps, fold into per-batch global scratch ----
    if (tid < QLEN) {
        float v = red[tid];
#pragma unroll
        for (int w = 1; w < WARPS; w++) v = fmaxf(v, red[w * QLEN + tid]);
        atomicMax(&g_qmax[b * QLEN + tid], ordenc(v));
    }
    __threadfence();

    // ---- Last CTA per batch finishes: sum over q, write out, reset scratch ----
    if (tid == 0)
        s_last = (atomicAdd(&g_count[b], 1) == SPLITS - 1) ? 1 : 0;
    __syncthreads();

    if (s_last) {
        if (tid < QLEN) {
            // atomic read-modify-write with identity to get a coherent value
            unsigned o = atomicMax(&g_qmax[b * QLEN + tid], 0u);
            float v = orddec(o);
#pragma unroll
            for (int off = 16; off > 0; off >>= 1)
                v += __shfl_xor_sync(0xffffffffu, v, off);
            if (tid == 0) out[b] = v;
            // reset scratch for the next (graph-replayed) call
            g_qmax[b * QLEN + tid] = 0u;
        }
        if (tid == 0) g_count[b] = 0;
    }
}

// ---------------------------------------------------------------------------
extern "C" void kernel_launch(void* const* d_in, const int* in_sizes, int n_in,
                              void* d_out, int out_size) {
    const float* qv   = (const float*)d_in[0];   // [64,32,128] f32
    const float* dv   = (const float*)d_in[1];   // [64,4096,128] f32
    const int*   mask = (const int*)d_in[2];     // [64,4096] i32
    float* out = (float*)d_out;                  // [64] f32

    dim3 grid(SPLITS, BATCH);
    li_score_kernel<<<grid, THREADS>>>(qv, dv, mask, out);
}